// round 1
// baseline (speedup 1.0000x reference)
#include <cuda_runtime.h>
#include <math.h>

// Problem constants
#define Ssz 1024
#define Bsz 4
#define Esz 1024
#define Hsz 16
#define Msz 128
#define Vsz 64
#define NCOLS (Hsz * (2 * Msz + Vsz))   // 5120 combined q/k/v output columns
#define SBE (Ssz * Bsz * Esz)           // 4194304

// Scratch (allocation-free rule: static __device__ arrays)
__device__ float2 g_q[Bsz * Hsz * Ssz * Msz];    // (b,h,s,m)
__device__ float2 g_k[Bsz * Hsz * Ssz * Msz];
__device__ float2 g_v[Bsz * Hsz * Ssz * Vsz];    // (b,h,s,v)
__device__ float2 g_upd[Ssz * Bsz * Esz];        // (s,b,h*V+v)

// ---------------------------------------------------------------------------
// Kernel 1: fused complex QKV projection.
// C[r,c] = sum_e x[r,e] * W[c,e] (complex), r = s*B+b (4096), c in [0,5120).
// 64x64 tile, 16 K-chunk, 256 threads, 4x4 complex micro-tile.
// ---------------------------------------------------------------------------
__global__ __launch_bounds__(256) void proj_gemm(
    const float* __restrict__ xre, const float* __restrict__ xim,
    const float* __restrict__ wq_re, const float* __restrict__ wq_im,
    const float* __restrict__ wk_re, const float* __restrict__ wk_im,
    const float* __restrict__ wv_re, const float* __restrict__ wv_im)
{
    __shared__ float2 As[16][66];
    __shared__ float2 Bs[16][66];
    __shared__ const float* rowRe[64];
    __shared__ const float* rowIm[64];

    const int rowBase = blockIdx.x * 64;
    const int colBase = blockIdx.y * 64;
    const int tid = threadIdx.x;

    if (tid < 64) {
        int c = colBase + tid;
        int h = c / 320;
        int j = c % 320;
        const float* re;
        const float* im;
        if (j < Msz) {
            re = wq_re + (h * Msz + j) * Esz;
            im = wq_im + (h * Msz + j) * Esz;
        } else if (j < 2 * Msz) {
            re = wk_re + (h * Msz + (j - Msz)) * Esz;
            im = wk_im + (h * Msz + (j - Msz)) * Esz;
        } else {
            re = wv_re + (h * Vsz + (j - 2 * Msz)) * Esz;
            im = wv_im + (h * Vsz + (j - 2 * Msz)) * Esz;
        }
        rowRe[tid] = re;
        rowIm[tid] = im;
    }
    __syncthreads();

    const int tx = tid & 15;
    const int ty = tid >> 4;
    const int lrow = tid >> 2;        // 0..63 : which tile row/col this thread loads
    const int lkq  = (tid & 3) * 4;   // 0,4,8,12 : k offset within chunk

    const float* aRe = xre + (rowBase + lrow) * Esz + lkq;
    const float* aIm = xim + (rowBase + lrow) * Esz + lkq;
    const float* bRe = rowRe[lrow] + lkq;
    const float* bIm = rowIm[lrow] + lkq;

    float2 acc[4][4];
#pragma unroll
    for (int i = 0; i < 4; ++i)
#pragma unroll
        for (int j = 0; j < 4; ++j) acc[i][j] = make_float2(0.f, 0.f);

    for (int kk = 0; kk < Esz; kk += 16) {
        float4 ar = *(const float4*)(aRe + kk);
        float4 ai = *(const float4*)(aIm + kk);
        float4 br = *(const float4*)(bRe + kk);
        float4 bi = *(const float4*)(bIm + kk);
        As[lkq + 0][lrow] = make_float2(ar.x, ai.x);
        As[lkq + 1][lrow] = make_float2(ar.y, ai.y);
        As[lkq + 2][lrow] = make_float2(ar.z, ai.z);
        As[lkq + 3][lrow] = make_float2(ar.w, ai.w);
        Bs[lkq + 0][lrow] = make_float2(br.x, bi.x);
        Bs[lkq + 1][lrow] = make_float2(br.y, bi.y);
        Bs[lkq + 2][lrow] = make_float2(br.z, bi.z);
        Bs[lkq + 3][lrow] = make_float2(br.w, bi.w);
        __syncthreads();

#pragma unroll
        for (int k = 0; k < 16; ++k) {
            float4 a0 = *(const float4*)&As[k][ty * 4];
            float4 a1 = *(const float4*)&As[k][ty * 4 + 2];
            float4 b0 = *(const float4*)&Bs[k][tx * 4];
            float4 b1 = *(const float4*)&Bs[k][tx * 4 + 2];
            float2 a[4] = { {a0.x, a0.y}, {a0.z, a0.w}, {a1.x, a1.y}, {a1.z, a1.w} };
            float2 b[4] = { {b0.x, b0.y}, {b0.z, b0.w}, {b1.x, b1.y}, {b1.z, b1.w} };
#pragma unroll
            for (int i = 0; i < 4; ++i)
#pragma unroll
                for (int j = 0; j < 4; ++j) {
                    acc[i][j].x = fmaf(a[i].x, b[j].x, acc[i][j].x);
                    acc[i][j].x = fmaf(-a[i].y, b[j].y, acc[i][j].x);
                    acc[i][j].y = fmaf(a[i].x, b[j].y, acc[i][j].y);
                    acc[i][j].y = fmaf(a[i].y, b[j].x, acc[i][j].y);
                }
        }
        __syncthreads();
    }

#pragma unroll
    for (int j = 0; j < 4; ++j) {
        int c = colBase + tx * 4 + j;
        int h = c / 320;
        int jj = c % 320;
#pragma unroll
        for (int i = 0; i < 4; ++i) {
            int r = rowBase + ty * 4 + i;
            int s = r >> 2;
            int b = r & 3;
            float2 val = acc[i][j];
            if (jj < Msz)
                g_q[((b * Hsz + h) * Ssz + s) * Msz + jj] = val;
            else if (jj < 2 * Msz)
                g_k[((b * Hsz + h) * Ssz + s) * Msz + (jj - Msz)] = val;
            else
                g_v[((b * Hsz + h) * Ssz + s) * Vsz + (jj - 2 * Msz)] = val;
        }
    }
}

// ---------------------------------------------------------------------------
// Kernel 2: causal complex attention with |score| softmax (flash-style).
// Block: 1024 threads = 32 warps, each warp owns one query row of a 32-row
// tile. Grid (S/32, B*H). Online softmax over key tiles of 32.
// ---------------------------------------------------------------------------
__global__ __launch_bounds__(1024) void attn_kernel()
{
    extern __shared__ char smraw[];
    float2* q_s = (float2*)smraw;            // [32][128]
    float2* k_s = q_s + 32 * 128;            // [128][33]  (transposed, padded)
    float2* v_s = k_s + 128 * 33;            // [32][64]

    const int tile = blockIdx.x;             // 0..31
    const int bh = blockIdx.y;               // b*H+h, 0..63
    const int warp = threadIdx.x >> 5;
    const int lane = threadIdx.x & 31;
    const int srow = tile * 32 + warp;

    const float2* qbase = g_q + ((long)bh * Ssz + tile * 32) * Msz;
    for (int i = threadIdx.x; i < 32 * 128; i += 1024)
        q_s[i] = qbase[i];                   // q_s[row][m], row-major 128

    float run_max = -INFINITY;
    float run_sum = 0.f;
    float2 acc0 = make_float2(0.f, 0.f);
    float2 acc1 = make_float2(0.f, 0.f);
    const float inv_sqrt_m = 0.088388347648318447f;   // 1/sqrt(128)

    for (int kt = 0; kt <= tile; ++kt) {
        const float2* kbase = g_k + ((long)bh * Ssz + kt * 32) * Msz;
        for (int i = threadIdx.x; i < 32 * 128; i += 1024) {
            int t = i >> 7, m = i & 127;
            k_s[m * 33 + t] = kbase[i];
        }
        const float2* vbase = g_v + ((long)bh * Ssz + kt * 32) * Vsz;
        for (int i = threadIdx.x; i < 32 * 64; i += 1024)
            v_s[i] = vbase[i];
        __syncthreads();

        // complex dot: score(row srow, key kt*32+lane)
        float sr = 0.f, si = 0.f;
        const float2* qrow = q_s + warp * 128;
#pragma unroll 8
        for (int m = 0; m < 128; ++m) {
            float2 qv = qrow[m];
            float2 kv = k_s[m * 33 + lane];
            sr = fmaf(qv.x, kv.x, sr);
            sr = fmaf(-qv.y, kv.y, sr);
            si = fmaf(qv.x, kv.y, si);
            si = fmaf(qv.y, kv.x, si);
        }
        int tcol = kt * 32 + lane;
        float amp = (tcol <= srow) ? sqrtf(sr * sr + si * si) * inv_sqrt_m
                                   : -INFINITY;
        // warp-wide online softmax
        float tmax = amp;
#pragma unroll
        for (int o = 16; o > 0; o >>= 1)
            tmax = fmaxf(tmax, __shfl_xor_sync(0xffffffffu, tmax, o));
        float nmax = fmaxf(run_max, tmax);
        float corr = __expf(run_max - nmax);      // run_max=-inf,nmax finite -> 0
        float p = __expf(amp - nmax);             // amp=-inf -> 0
        float psum = p;
#pragma unroll
        for (int o = 16; o > 0; o >>= 1)
            psum += __shfl_xor_sync(0xffffffffu, psum, o);
        run_sum = run_sum * corr + psum;
        run_max = nmax;
        acc0.x *= corr; acc0.y *= corr;
        acc1.x *= corr; acc1.y *= corr;

#pragma unroll
        for (int t = 0; t < 32; ++t) {
            float pt = __shfl_sync(0xffffffffu, p, t);
            float2 v0 = v_s[t * 64 + lane];
            float2 v1 = v_s[t * 64 + lane + 32];
            acc0.x = fmaf(pt, v0.x, acc0.x);
            acc0.y = fmaf(pt, v0.y, acc0.y);
            acc1.x = fmaf(pt, v1.x, acc1.x);
            acc1.y = fmaf(pt, v1.y, acc1.y);
        }
        __syncthreads();
    }

    float inv = 1.0f / run_sum;
    int b = bh >> 4;     // H = 16
    int h = bh & 15;
    long base = ((long)srow * Bsz + b) * Esz + h * Vsz;
    g_upd[base + lane]      = make_float2(acc0.x * inv, acc0.y * inv);
    g_upd[base + lane + 32] = make_float2(acc1.x * inv, acc1.y * inv);
}

// ---------------------------------------------------------------------------
// Kernel 3: output projection + residual.
// out[r,f] = sum_e upd[r,e] * wo[e,f] + x[r,f]  (complex);
// output stacked: real block then imag block.
// ---------------------------------------------------------------------------
__global__ __launch_bounds__(256) void out_gemm(
    const float* __restrict__ wo_re, const float* __restrict__ wo_im,
    const float* __restrict__ xre, const float* __restrict__ xim,
    float* __restrict__ out)
{
    __shared__ float2 As[16][66];
    __shared__ float2 Bs[16][66];

    const int rowBase = blockIdx.x * 64;
    const int colBase = blockIdx.y * 64;
    const int tid = threadIdx.x;
    const int tx = tid & 15;
    const int ty = tid >> 4;

    // A loader: 4 threads per row, each 4 complex elems
    const int lrow = tid >> 2;
    const int lkq  = (tid & 3) * 4;
    const float2* aP = g_upd + (long)(rowBase + lrow) * Esz + lkq;

    // B loader: thread -> (k = tid>>4, f quad = (tid&15)*4)
    const int lk = tid >> 4;
    const int lf = (tid & 15) * 4;

    float2 acc[4][4];
#pragma unroll
    for (int i = 0; i < 4; ++i)
#pragma unroll
        for (int j = 0; j < 4; ++j) acc[i][j] = make_float2(0.f, 0.f);

    for (int kk = 0; kk < Esz; kk += 16) {
        float4 a01 = *(const float4*)(aP + kk);       // complex lkq, lkq+1
        float4 a23 = *(const float4*)(aP + kk + 2);   // complex lkq+2, lkq+3
        As[lkq + 0][lrow] = make_float2(a01.x, a01.y);
        As[lkq + 1][lrow] = make_float2(a01.z, a01.w);
        As[lkq + 2][lrow] = make_float2(a23.x, a23.y);
        As[lkq + 3][lrow] = make_float2(a23.z, a23.w);

        float4 br = *(const float4*)(wo_re + (long)(kk + lk) * Esz + colBase + lf);
        float4 bi = *(const float4*)(wo_im + (long)(kk + lk) * Esz + colBase + lf);
        Bs[lk][lf + 0] = make_float2(br.x, bi.x);
        Bs[lk][lf + 1] = make_float2(br.y, bi.y);
        Bs[lk][lf + 2] = make_float2(br.z, bi.z);
        Bs[lk][lf + 3] = make_float2(br.w, bi.w);
        __syncthreads();

#pragma unroll
        for (int k = 0; k < 16; ++k) {
            float4 a0 = *(const float4*)&As[k][ty * 4];
            float4 a1 = *(const float4*)&As[k][ty * 4 + 2];
            float4 b0 = *(const float4*)&Bs[k][tx * 4];
            float4 b1 = *(const float4*)&Bs[k][tx * 4 + 2];
            float2 a[4] = { {a0.x, a0.y}, {a0.z, a0.w}, {a1.x, a1.y}, {a1.z, a1.w} };
            float2 b[4] = { {b0.x, b0.y}, {b0.z, b0.w}, {b1.x, b1.y}, {b1.z, b1.w} };
#pragma unroll
            for (int i = 0; i < 4; ++i)
#pragma unroll
                for (int j = 0; j < 4; ++j) {
                    acc[i][j].x = fmaf(a[i].x, b[j].x, acc[i][j].x);
                    acc[i][j].x = fmaf(-a[i].y, b[j].y, acc[i][j].x);
                    acc[i][j].y = fmaf(a[i].x, b[j].y, acc[i][j].y);
                    acc[i][j].y = fmaf(a[i].y, b[j].x, acc[i][j].y);
                }
        }
        __syncthreads();
    }

#pragma unroll
    for (int i = 0; i < 4; ++i) {
        int r = rowBase + ty * 4 + i;
#pragma unroll
        for (int j = 0; j < 4; ++j) {
            int c = colBase + tx * 4 + j;
            long idx = (long)r * Esz + c;
            out[idx]       = acc[i][j].x + xre[idx];
            out[SBE + idx] = acc[i][j].y + xim[idx];
        }
    }
}

// ---------------------------------------------------------------------------
extern "C" void kernel_launch(void* const* d_in, const int* in_sizes, int n_in,
                              void* d_out, int out_size)
{
    const float* logits_re = (const float*)d_in[0];
    const float* logits_im = (const float*)d_in[1];
    const float* wq_re = (const float*)d_in[2];
    const float* wq_im = (const float*)d_in[3];
    const float* wk_re = (const float*)d_in[4];
    const float* wk_im = (const float*)d_in[5];
    const float* wv_re = (const float*)d_in[6];
    const float* wv_im = (const float*)d_in[7];
    const float* wo_re = (const float*)d_in[8];
    const float* wo_im = (const float*)d_in[9];
    float* out = (float*)d_out;

    // QKV projection: rows 4096/64=64, cols 5120/64=80
    proj_gemm<<<dim3(64, 80), 256>>>(logits_re, logits_im,
                                     wq_re, wq_im, wk_re, wk_im, wv_re, wv_im);

    // Attention: 32 query tiles x 64 (b,h)
    const int attn_smem = (32 * 128 + 128 * 33 + 32 * 64) * (int)sizeof(float2);
    static bool attr_set = false;
    if (!attr_set) {
        cudaFuncSetAttribute(attn_kernel,
                             cudaFuncAttributeMaxDynamicSharedMemorySize,
                             attn_smem);
        attr_set = true;
    }
    attn_kernel<<<dim3(32, 64), 1024, attn_smem>>>();

    // Output projection + residual: rows 64, cols 1024/64=16
    out_gemm<<<dim3(64, 16), 256>>>(wo_re, wo_im, logits_re, logits_im, out);
}